// round 2
// baseline (speedup 1.0000x reference)
#include <cuda_runtime.h>
#include <math.h>

#define NN 512
#define CS 384
#define CZ 128
#define NH 16
#define HD 24
#define EPS 1e-5f

// ---------------- scratch (static device allocations; no runtime alloc) ----------------
__device__ float g_an[NN * CS];               // LN(a)
__device__ float g_qkvg[NN * 4 * CS];         // per row: [q(384, pre-scaled) | k | v | g(sigmoid)]
__device__ float g_bias[(size_t)NH * NN * NN];// pair bias [h][i][j]
__device__ float g_att[NN * CS];              // gated attention output [n][h*24+d]
__device__ float g_gwT[NH * CZ];              // (g_z * Wz) transposed: [h][c]
__device__ float g_colsum[NH];
__device__ float g_cconst[NH];

// ---------------- K0: fold LN(z) constants into Wz ----------------
__global__ void prep_kernel(const float* __restrict__ gz, const float* __restrict__ bzln,
                            const float* __restrict__ Wz, const float* __restrict__ bz) {
    int c = threadIdx.x;  // 128
    float g = gz[c];
    #pragma unroll
    for (int h = 0; h < NH; h++) g_gwT[h * CZ + c] = g * Wz[c * NH + h];
    __syncthreads();
    if (c < NH) {
        float cs = 0.f, ct = bz[c];
        for (int k = 0; k < CZ; k++) {
            cs += g_gwT[c * CZ + k];
            ct += bzln[k] * Wz[k * NH + c];
        }
        g_colsum[c] = cs;
        g_cconst[c] = ct;
    }
}

// ---------------- K1: LN(a) ----------------
__global__ void ln_a_kernel(const float* __restrict__ a, const float* __restrict__ ga,
                            const float* __restrict__ ba) {
    int row = blockIdx.x, t = threadIdx.x;  // 128 threads
    const float* x = a + row * CS;
    float v0 = x[t], v1 = x[t + 128], v2 = x[t + 256];
    float s = v0 + v1 + v2;
    float q = v0 * v0 + v1 * v1 + v2 * v2;
    __shared__ float rs[4], rq[4];
    #pragma unroll
    for (int o = 16; o > 0; o >>= 1) {
        s += __shfl_xor_sync(0xFFFFFFFFu, s, o);
        q += __shfl_xor_sync(0xFFFFFFFFu, q, o);
    }
    if ((t & 31) == 0) { rs[t >> 5] = s; rq[t >> 5] = q; }
    __syncthreads();
    float S = rs[0] + rs[1] + rs[2] + rs[3];
    float Q = rq[0] + rq[1] + rq[2] + rq[3];
    float m = S * (1.f / CS);
    float var = Q * (1.f / CS) - m * m;
    float r = rsqrtf(var + EPS);
    float* o = g_an + row * CS;
    o[t]       = (v0 - m) * r * ga[t]       + ba[t];
    o[t + 128] = (v1 - m) * r * ga[t + 128] + ba[t + 128];
    o[t + 256] = (v2 - m) * r * ga[t + 256] + ba[t + 256];
}

// ---------------- K2: fused QKVG GEMMs  (g_an[512,384] @ W[384,384] x4) ----------------
// grid (6, 8, 4): x = 64-col tile, y = 64-row tile, z = which matrix (q,k,v,g)
__global__ void qkvg_kernel(const float* __restrict__ Wq, const float* __restrict__ Wk,
                            const float* __restrict__ Wv, const float* __restrict__ Wg,
                            const float* __restrict__ bg) {
    __shared__ float As[16][64];
    __shared__ float Bs[16][68];
    int mat = blockIdx.z;
    const float* B = (mat == 0) ? Wq : (mat == 1) ? Wk : (mat == 2) ? Wv : Wg;
    int bm = blockIdx.y * 64, bn = blockIdx.x * 64;
    int tid = threadIdx.x;        // 256
    int tx = tid & 15, ty = tid >> 4;
    int arow = tid >> 2, acol4 = (tid & 3) * 4;
    int brow = tid >> 4, bcol4 = (tid & 15) * 4;
    float acc[4][4] = {};

    for (int k0 = 0; k0 < CS; k0 += 16) {
        float4 av = *(const float4*)(g_an + (bm + arow) * CS + k0 + acol4);
        As[acol4 + 0][arow] = av.x;
        As[acol4 + 1][arow] = av.y;
        As[acol4 + 2][arow] = av.z;
        As[acol4 + 3][arow] = av.w;
        float4 bv = *(const float4*)(B + (k0 + brow) * CS + bn + bcol4);
        *(float4*)&Bs[brow][bcol4] = bv;
        __syncthreads();
        #pragma unroll
        for (int kk = 0; kk < 16; kk++) {
            float4 a4 = *(const float4*)&As[kk][ty * 4];
            float4 b4 = *(const float4*)&Bs[kk][tx * 4];
            float af[4] = {a4.x, a4.y, a4.z, a4.w};
            float bf[4] = {b4.x, b4.y, b4.z, b4.w};
            #pragma unroll
            for (int i = 0; i < 4; i++)
                #pragma unroll
                for (int j = 0; j < 4; j++)
                    acc[i][j] += af[i] * bf[j];
        }
        __syncthreads();
    }
    int colbase = mat * CS + bn + tx * 4;
    #pragma unroll
    for (int i = 0; i < 4; i++) {
        int row = bm + ty * 4 + i;
        float* out = g_qkvg + row * (4 * CS) + colbase;
        #pragma unroll
        for (int j = 0; j < 4; j++) {
            float v = acc[i][j];
            if (mat == 0) v *= 0.2041241452319315f;  // 1/sqrt(24)
            else if (mat == 3) v = 1.f / (1.f + __expf(-(v + bg[bn + tx * 4 + j])));
            out[j] = v;
        }
    }
}

// ---------------- K3: fused LN(z) + pair-bias projection ----------------
// grid (4, 512): y = i, x = 128-wide j tile. 256 threads. dynamic smem 76800B.
__global__ void pair_bias_kernel(const float* __restrict__ z) {
    extern __shared__ float smem[];
    float* zs    = smem;                 // 128 rows x 132 (padded)
    float* gwTs  = zs + 128 * 132;       // 16 x 128
    float* smean = gwTs + NH * CZ;       // 128
    float* srstd = smean + 128;          // 128
    __shared__ float cs_s[NH], cc_s[NH];

    int i  = blockIdx.y;
    int j0 = blockIdx.x * 128;
    int tid = threadIdx.x;               // 256

    for (int idx = tid; idx < NH * CZ; idx += 256) gwTs[idx] = g_gwT[idx];
    if (tid < NH) { cs_s[tid] = g_colsum[tid]; cc_s[tid] = g_cconst[tid]; }

    // z tile [128 j][128 c] is contiguous in gmem -> coalesced float4 copy
    const float4* src = (const float4*)(z + ((size_t)i * NN + j0) * CZ);
    for (int idx = tid; idx < 128 * 32; idx += 256) {
        int row = idx >> 5, c4 = idx & 31;
        *(float4*)(zs + row * 132 + c4 * 4) = src[idx];
    }
    __syncthreads();

    if (tid < 128) {
        const float* zr = zs + tid * 132;
        float s = 0.f, q = 0.f;
        #pragma unroll 8
        for (int c = 0; c < 128; c++) { float v = zr[c]; s += v; q += v * v; }
        float m = s * (1.f / 128.f);
        float var = q * (1.f / 128.f) - m * m;
        smean[tid] = m;
        srstd[tid] = rsqrtf(var + EPS);
    }
    __syncthreads();

    int j = tid >> 1;
    int half = tid & 1;
    const float* zr = zs + j * 132;
    float acc[8] = {0, 0, 0, 0, 0, 0, 0, 0};
    #pragma unroll 4
    for (int c4 = 0; c4 < 128; c4 += 4) {
        float4 zv = *(const float4*)(zr + c4);
        #pragma unroll
        for (int hh = 0; hh < 8; hh++) {
            float4 wv = *(const float4*)(gwTs + (half * 8 + hh) * CZ + c4);
            acc[hh] += zv.x * wv.x + zv.y * wv.y + zv.z * wv.z + zv.w * wv.w;
        }
    }
    float m = smean[j], r = srstd[j];
    #pragma unroll
    for (int hh = 0; hh < 8; hh++) {
        int h = half * 8 + hh;
        float v = r * (acc[hh] - m * cs_s[h]) + cc_s[h];
        g_bias[((size_t)h * NN + i) * NN + j0 + j] = v;
    }
}

// ---------------- K4: attention (scores + bias, softmax, PV, gate) ----------------
// grid (16 q-tiles, 16 heads), 256 threads, dynamic smem 106368B.
__global__ void attn_kernel() {
    extern __shared__ float smem[];
    float* ks   = smem;              // 512 x 25
    float* vs   = ks + 512 * 25;     // 512 x 25
    float* qs   = vs + 512 * 25;     // 32 x 25
    float* wbuf = qs + 32 * 25;      // 8 x 24

    int h  = blockIdx.y;
    int q0 = blockIdx.x * 32;
    int tid = threadIdx.x, lane = tid & 31, warp = tid >> 5;

    for (int idx = tid; idx < 512 * 24; idx += 256) {
        int n = idx / 24, d = idx - n * 24;
        const float* row = g_qkvg + n * (4 * CS);
        ks[n * 25 + d] = row[CS + h * HD + d];
        vs[n * 25 + d] = row[2 * CS + h * HD + d];
    }
    for (int idx = tid; idx < 32 * 24; idx += 256) {
        int n = idx / 24, d = idx - n * 24;
        qs[n * 25 + d] = g_qkvg[(q0 + n) * (4 * CS) + h * HD + d];
    }
    __syncthreads();

    for (int qr = 0; qr < 4; qr++) {
        int qlocal = warp * 4 + qr;
        int qrow = q0 + qlocal;
        const float* qp = qs + qlocal * 25;
        const float* brow = g_bias + ((size_t)h * NN + qrow) * NN;

        float e[16];
        float mx = -1e30f;
        #pragma unroll
        for (int jj = 0; jj < 16; jj++) {
            int j = jj * 32 + lane;
            const float* kp = ks + j * 25;
            float s = 0.f;
            #pragma unroll
            for (int d = 0; d < 24; d++) s += qp[d] * kp[d];
            s += brow[j];
            e[jj] = s;
            mx = fmaxf(mx, s);
        }
        #pragma unroll
        for (int o = 16; o > 0; o >>= 1) mx = fmaxf(mx, __shfl_xor_sync(0xFFFFFFFFu, mx, o));
        float sumv = 0.f;
        #pragma unroll
        for (int jj = 0; jj < 16; jj++) { e[jj] = __expf(e[jj] - mx); sumv += e[jj]; }
        #pragma unroll
        for (int o = 16; o > 0; o >>= 1) sumv += __shfl_xor_sync(0xFFFFFFFFu, sumv, o);
        float inv = 1.f / sumv;

        float acc[24];
        #pragma unroll
        for (int d = 0; d < 24; d++) acc[d] = 0.f;
        #pragma unroll
        for (int jj = 0; jj < 16; jj++) {
            int j = jj * 32 + lane;
            const float* vp = vs + j * 25;
            float p = e[jj];
            #pragma unroll
            for (int d = 0; d < 24; d++) acc[d] += p * vp[d];
        }
        float* wb = wbuf + warp * 24;
        #pragma unroll
        for (int d = 0; d < 24; d++) {
            float v = acc[d];
            v += __shfl_xor_sync(0xFFFFFFFFu, v, 16);
            v += __shfl_xor_sync(0xFFFFFFFFu, v, 8);
            v += __shfl_xor_sync(0xFFFFFFFFu, v, 4);
            v += __shfl_xor_sync(0xFFFFFFFFu, v, 2);
            v += __shfl_xor_sync(0xFFFFFFFFu, v, 1);
            if (lane == 0) wb[d] = v;
        }
        __syncwarp();
        if (lane < 24) {
            float ov = wb[lane] * inv;
            float gv = g_qkvg[qrow * (4 * CS) + 3 * CS + h * HD + lane];
            g_att[qrow * CS + h * HD + lane] = ov * gv;
        }
        __syncwarp();
    }
}

// ---------------- K5: output projection (g_att @ Wo + bo) ----------------
__global__ void outproj_kernel(const float* __restrict__ Wo, const float* __restrict__ bo,
                               float* __restrict__ out) {
    __shared__ float As[16][64];
    __shared__ float Bs[16][68];
    int bm = blockIdx.y * 64, bn = blockIdx.x * 64;
    int tid = threadIdx.x;
    int tx = tid & 15, ty = tid >> 4;
    int arow = tid >> 2, acol4 = (tid & 3) * 4;
    int brow = tid >> 4, bcol4 = (tid & 15) * 4;
    float acc[4][4] = {};

    for (int k0 = 0; k0 < CS; k0 += 16) {
        float4 av = *(const float4*)(g_att + (bm + arow) * CS + k0 + acol4);
        As[acol4 + 0][arow] = av.x;
        As[acol4 + 1][arow] = av.y;
        As[acol4 + 2][arow] = av.z;
        As[acol4 + 3][arow] = av.w;
        float4 bv = *(const float4*)(Wo + (k0 + brow) * CS + bn + bcol4);
        *(float4*)&Bs[brow][bcol4] = bv;
        __syncthreads();
        #pragma unroll
        for (int kk = 0; kk < 16; kk++) {
            float4 a4 = *(const float4*)&As[kk][ty * 4];
            float4 b4 = *(const float4*)&Bs[kk][tx * 4];
            float af[4] = {a4.x, a4.y, a4.z, a4.w};
            float bf[4] = {b4.x, b4.y, b4.z, b4.w};
            #pragma unroll
            for (int i = 0; i < 4; i++)
                #pragma unroll
                for (int j = 0; j < 4; j++)
                    acc[i][j] += af[i] * bf[j];
        }
        __syncthreads();
    }
    #pragma unroll
    for (int i = 0; i < 4; i++) {
        int row = bm + ty * 4 + i;
        float* o = out + row * CS + bn + tx * 4;
        #pragma unroll
        for (int j = 0; j < 4; j++)
            o[j] = acc[i][j] + bo[bn + tx * 4 + j];
    }
}

// ---------------- launch ----------------
extern "C" void kernel_launch(void* const* d_in, const int* in_sizes, int n_in,
                              void* d_out, int out_size) {
    (void)in_sizes; (void)n_in; (void)out_size;
    const float* a   = (const float*)d_in[0];
    const float* z   = (const float*)d_in[1];
    const float* g_a = (const float*)d_in[2];
    const float* b_a = (const float*)d_in[3];
    const float* g_z = (const float*)d_in[4];
    const float* b_z = (const float*)d_in[5];
    const float* Wz  = (const float*)d_in[6];
    const float* bz  = (const float*)d_in[7];
    const float* Wq  = (const float*)d_in[8];
    const float* Wk  = (const float*)d_in[9];
    const float* Wv  = (const float*)d_in[10];
    const float* Wg  = (const float*)d_in[11];
    const float* bg  = (const float*)d_in[12];
    const float* Wo  = (const float*)d_in[13];
    const float* bo  = (const float*)d_in[14];
    float* out = (float*)d_out;

    cudaFuncSetAttribute(pair_bias_kernel, cudaFuncAttributeMaxDynamicSharedMemorySize, 76800);
    cudaFuncSetAttribute(attn_kernel, cudaFuncAttributeMaxDynamicSharedMemorySize, 106368);

    prep_kernel<<<1, 128>>>(g_z, b_z, Wz, bz);
    ln_a_kernel<<<NN, 128>>>(a, g_a, b_a);
    qkvg_kernel<<<dim3(6, 8, 4), 256>>>(Wq, Wk, Wv, Wg, bg);
    pair_bias_kernel<<<dim3(4, NN), 256, 76800>>>(z);
    attn_kernel<<<dim3(16, 16), 256, 106368>>>();
    outproj_kernel<<<dim3(6, 8), 256>>>(Wo, bo, out);
}

// round 4
// speedup vs baseline: 1.3442x; 1.3442x over previous
#include <cuda_runtime.h>
#include <math.h>

#define NN 512
#define CS 384
#define CZ 128
#define NH 16
#define HD 24
#define EPS 1e-5f
#define ZST 132   // padded z row stride in floats; 16B-aligned, (ZST/4)%8==1 -> LDS.128 conflict-free

// ---------------- scratch (static device allocations; no runtime alloc) ----------------
__device__ float g_an[NN * CS];               // LN(a)
__device__ float g_qkvg[NN * 4 * CS];         // per row: [q(384, pre-scaled) | k | v | g(sigmoid)]
__device__ float g_bias[(size_t)NH * NN * NN];// pair bias [h][i][j]
__device__ float g_att[NN * CS];              // gated attention output [n][h*24+d]
__device__ float g_gwT[NH * CZ];              // (g_z * Wz) transposed: [h][c]
__device__ float g_colsum[NH];
__device__ float g_cconst[NH];

// ---------------- K0: fold LN(z) constants into Wz ----------------
__global__ void prep_kernel(const float* __restrict__ gz, const float* __restrict__ bzln,
                            const float* __restrict__ Wz, const float* __restrict__ bz) {
    int c = threadIdx.x;  // 128
    float g = gz[c];
    #pragma unroll
    for (int h = 0; h < NH; h++) g_gwT[h * CZ + c] = g * Wz[c * NH + h];
    __syncthreads();
    if (c < NH) {
        float cs = 0.f, ct = bz[c];
        for (int k = 0; k < CZ; k++) {
            cs += g_gwT[c * CZ + k];
            ct += bzln[k] * Wz[k * NH + c];
        }
        g_colsum[c] = cs;
        g_cconst[c] = ct;
    }
}

// ---------------- K1: LN(a) ----------------
__global__ void ln_a_kernel(const float* __restrict__ a, const float* __restrict__ ga,
                            const float* __restrict__ ba) {
    int row = blockIdx.x, t = threadIdx.x;  // 128 threads
    const float* x = a + row * CS;
    float v0 = x[t], v1 = x[t + 128], v2 = x[t + 256];
    float s = v0 + v1 + v2;
    float q = v0 * v0 + v1 * v1 + v2 * v2;
    __shared__ float rs[4], rq[4];
    #pragma unroll
    for (int o = 16; o > 0; o >>= 1) {
        s += __shfl_xor_sync(0xFFFFFFFFu, s, o);
        q += __shfl_xor_sync(0xFFFFFFFFu, q, o);
    }
    if ((t & 31) == 0) { rs[t >> 5] = s; rq[t >> 5] = q; }
    __syncthreads();
    float S = rs[0] + rs[1] + rs[2] + rs[3];
    float Q = rq[0] + rq[1] + rq[2] + rq[3];
    float m = S * (1.f / CS);
    float var = Q * (1.f / CS) - m * m;
    float r = rsqrtf(var + EPS);
    float* o = g_an + row * CS;
    o[t]       = (v0 - m) * r * ga[t]       + ba[t];
    o[t + 128] = (v1 - m) * r * ga[t + 128] + ba[t + 128];
    o[t + 256] = (v2 - m) * r * ga[t + 256] + ba[t + 256];
}

// ---------------- K2: fused QKVG GEMMs  (g_an[512,384] @ W[384,384] x4) ----------------
__global__ void qkvg_kernel(const float* __restrict__ Wq, const float* __restrict__ Wk,
                            const float* __restrict__ Wv, const float* __restrict__ Wg,
                            const float* __restrict__ bg) {
    __shared__ float As[16][64];
    __shared__ float Bs[16][68];
    int mat = blockIdx.z;
    const float* B = (mat == 0) ? Wq : (mat == 1) ? Wk : (mat == 2) ? Wv : Wg;
    int bm = blockIdx.y * 64, bn = blockIdx.x * 64;
    int tid = threadIdx.x;        // 256
    int tx = tid & 15, ty = tid >> 4;
    int arow = tid >> 2, acol4 = (tid & 3) * 4;
    int brow = tid >> 4, bcol4 = (tid & 15) * 4;
    float acc[4][4] = {};

    for (int k0 = 0; k0 < CS; k0 += 16) {
        float4 av = *(const float4*)(g_an + (bm + arow) * CS + k0 + acol4);
        As[acol4 + 0][arow] = av.x;
        As[acol4 + 1][arow] = av.y;
        As[acol4 + 2][arow] = av.z;
        As[acol4 + 3][arow] = av.w;
        float4 bv = *(const float4*)(B + (k0 + brow) * CS + bn + bcol4);
        *(float4*)&Bs[brow][bcol4] = bv;
        __syncthreads();
        #pragma unroll
        for (int kk = 0; kk < 16; kk++) {
            float4 a4 = *(const float4*)&As[kk][ty * 4];
            float4 b4 = *(const float4*)&Bs[kk][tx * 4];
            float af[4] = {a4.x, a4.y, a4.z, a4.w};
            float bf[4] = {b4.x, b4.y, b4.z, b4.w};
            #pragma unroll
            for (int i = 0; i < 4; i++)
                #pragma unroll
                for (int j = 0; j < 4; j++)
                    acc[i][j] += af[i] * bf[j];
        }
        __syncthreads();
    }
    int colbase = mat * CS + bn + tx * 4;
    #pragma unroll
    for (int i = 0; i < 4; i++) {
        int row = bm + ty * 4 + i;
        float* out = g_qkvg + row * (4 * CS) + colbase;
        #pragma unroll
        for (int j = 0; j < 4; j++) {
            float v = acc[i][j];
            if (mat == 0) v *= 0.2041241452319315f;  // 1/sqrt(24)
            else if (mat == 3) v = 1.f / (1.f + __expf(-(v + bg[bn + tx * 4 + j])));
            out[j] = v;
        }
    }
}

// ---------------- K3: fused LN(z) + pair-bias projection (restructured) ----------------
// grid (8, 512): y = i, x = 64-wide j tile. 128 threads. dynamic smem 42496B.
// Thread tiling: warp hg owns 4 heads; lane owns rows {lane, lane+32}.
// Inner loop: 6 LDS.128 per 32 FMAs, weight loads warp-uniform (broadcast).
__global__ void pair_bias_kernel(const float* __restrict__ z) {
    extern __shared__ float smem[];
    float* zs    = smem;                 // 64 rows x ZST(132)
    float* ws    = zs + 64 * ZST;        // 16 x 128  (gwT)
    float* smean = ws + NH * CZ;         // 64
    float* srstd = smean + 64;           // 64
    __shared__ float cs_s[NH], cc_s[NH];

    int i  = blockIdx.y;
    int j0 = blockIdx.x * 64;
    int t = threadIdx.x;                 // 128
    int lane = t & 31, hg = t >> 5;

    // weights + constants
    #pragma unroll
    for (int k = 0; k < NH * CZ / 128; k++) ws[t + 128 * k] = g_gwT[t + 128 * k];
    if (t < NH) { cs_s[t] = g_colsum[t]; cc_s[t] = g_cconst[t]; }

    // stage z tile [64 j][128 c] — contiguous 32KB, fully coalesced float4 copy
    const float4* src = (const float4*)(z + ((size_t)i * NN + j0) * CZ);
    #pragma unroll
    for (int k = 0; k < 16; k++) {
        int idx = t + 128 * k;           // 0..2047
        int row = idx >> 5, c4 = idx & 31;
        *(float4*)(zs + row * ZST + c4 * 4) = src[idx];
    }
    __syncthreads();

    // stats: thread t -> row t>>1, half t&1; 4-way ILP + 1 shuffle
    {
        int row = t >> 1, half = t & 1;
        const float* zr = zs + row * ZST + half * 64;
        float s0 = 0, s1 = 0, s2 = 0, s3 = 0;
        float q0 = 0, q1 = 0, q2 = 0, q3 = 0;
        #pragma unroll
        for (int c = 0; c < 64; c += 4) {
            float4 v = *(const float4*)(zr + c);
            s0 += v.x; s1 += v.y; s2 += v.z; s3 += v.w;
            q0 += v.x * v.x; q1 += v.y * v.y; q2 += v.z * v.z; q3 += v.w * v.w;
        }
        float s = (s0 + s1) + (s2 + s3);
        float q = (q0 + q1) + (q2 + q3);
        s += __shfl_xor_sync(0xFFFFFFFFu, s, 1);
        q += __shfl_xor_sync(0xFFFFFFFFu, q, 1);
        if (half == 0) {
            float m = s * (1.f / 128.f);
            float var = q * (1.f / 128.f) - m * m;
            smean[row] = m;
            srstd[row] = rsqrtf(var + EPS);
        }
    }
    __syncthreads();

    // compute: 2 rows x 4 heads per thread
    const float* za = zs + lane * ZST;
    const float* zb = zs + (lane + 32) * ZST;
    const float* wb0 = ws + (hg * 4 + 0) * CZ;
    const float* wb1 = ws + (hg * 4 + 1) * CZ;
    const float* wb2 = ws + (hg * 4 + 2) * CZ;
    const float* wb3 = ws + (hg * 4 + 3) * CZ;
    float a0 = 0, a1 = 0, a2 = 0, a3 = 0;
    float b0 = 0, b1 = 0, b2 = 0, b3 = 0;
    #pragma unroll 4
    for (int c = 0; c < CZ; c += 4) {
        float4 va = *(const float4*)(za + c);
        float4 vb = *(const float4*)(zb + c);
        float4 w0 = *(const float4*)(wb0 + c);
        float4 w1 = *(const float4*)(wb1 + c);
        float4 w2 = *(const float4*)(wb2 + c);
        float4 w3 = *(const float4*)(wb3 + c);
        a0 += va.x * w0.x + va.y * w0.y + va.z * w0.z + va.w * w0.w;
        a1 += va.x * w1.x + va.y * w1.y + va.z * w1.z + va.w * w1.w;
        a2 += va.x * w2.x + va.y * w2.y + va.z * w2.z + va.w * w2.w;
        a3 += va.x * w3.x + va.y * w3.y + va.z * w3.z + va.w * w3.w;
        b0 += vb.x * w0.x + vb.y * w0.y + vb.z * w0.z + vb.w * w0.w;
        b1 += vb.x * w1.x + vb.y * w1.y + vb.z * w1.z + vb.w * w1.w;
        b2 += vb.x * w2.x + vb.y * w2.y + vb.z * w2.z + vb.w * w2.w;
        b3 += vb.x * w3.x + vb.y * w3.y + vb.z * w3.z + vb.w * w3.w;
    }
    float ma = smean[lane], ra = srstd[lane];
    float mb = smean[lane + 32], rb = srstd[lane + 32];
    float accA[4] = {a0, a1, a2, a3};
    float accB[4] = {b0, b1, b2, b3};
    #pragma unroll
    for (int hh = 0; hh < 4; hh++) {
        int h = hg * 4 + hh;
        float* dst = g_bias + ((size_t)h * NN + i) * NN + j0;
        dst[lane]      = ra * (accA[hh] - ma * cs_s[h]) + cc_s[h];
        dst[lane + 32] = rb * (accB[hh] - mb * cs_s[h]) + cc_s[h];
    }
}

// ---------------- K4: attention (scores + bias, softmax, PV, gate) ----------------
__global__ void attn_kernel() {
    extern __shared__ float smem[];
    float* ks   = smem;              // 512 x 25
    float* vs   = ks + 512 * 25;     // 512 x 25
    float* qs   = vs + 512 * 25;     // 32 x 25
    float* wbuf = qs + 32 * 25;      // 8 x 24

    int h  = blockIdx.y;
    int q0 = blockIdx.x * 32;
    int tid = threadIdx.x, lane = tid & 31, warp = tid >> 5;

    for (int idx = tid; idx < 512 * 24; idx += 256) {
        int n = idx / 24, d = idx - n * 24;
        const float* row = g_qkvg + n * (4 * CS);
        ks[n * 25 + d] = row[CS + h * HD + d];
        vs[n * 25 + d] = row[2 * CS + h * HD + d];
    }
    for (int idx = tid; idx < 32 * 24; idx += 256) {
        int n = idx / 24, d = idx - n * 24;
        qs[n * 25 + d] = g_qkvg[(q0 + n) * (4 * CS) + h * HD + d];
    }
    __syncthreads();

    for (int qr = 0; qr < 4; qr++) {
        int qlocal = warp * 4 + qr;
        int qrow = q0 + qlocal;
        const float* qp = qs + qlocal * 25;
        const float* brow = g_bias + ((size_t)h * NN + qrow) * NN;

        float e[16];
        float mx = -1e30f;
        #pragma unroll
        for (int jj = 0; jj < 16; jj++) {
            int j = jj * 32 + lane;
            const float* kp = ks + j * 25;
            float s = 0.f;
            #pragma unroll
            for (int d = 0; d < 24; d++) s += qp[d] * kp[d];
            s += brow[j];
            e[jj] = s;
            mx = fmaxf(mx, s);
        }
        #pragma unroll
        for (int o = 16; o > 0; o >>= 1) mx = fmaxf(mx, __shfl_xor_sync(0xFFFFFFFFu, mx, o));
        float sumv = 0.f;
        #pragma unroll
        for (int jj = 0; jj < 16; jj++) { e[jj] = __expf(e[jj] - mx); sumv += e[jj]; }
        #pragma unroll
        for (int o = 16; o > 0; o >>= 1) sumv += __shfl_xor_sync(0xFFFFFFFFu, sumv, o);
        float inv = 1.f / sumv;

        float acc[24];
        #pragma unroll
        for (int d = 0; d < 24; d++) acc[d] = 0.f;
        #pragma unroll
        for (int jj = 0; jj < 16; jj++) {
            int j = jj * 32 + lane;
            const float* vp = vs + j * 25;
            float p = e[jj];
            #pragma unroll
            for (int d = 0; d < 24; d++) acc[d] += p * vp[d];
        }
        float* wb = wbuf + warp * 24;
        #pragma unroll
        for (int d = 0; d < 24; d++) {
            float v = acc[d];
            v += __shfl_xor_sync(0xFFFFFFFFu, v, 16);
            v += __shfl_xor_sync(0xFFFFFFFFu, v, 8);
            v += __shfl_xor_sync(0xFFFFFFFFu, v, 4);
            v += __shfl_xor_sync(0xFFFFFFFFu, v, 2);
            v += __shfl_xor_sync(0xFFFFFFFFu, v, 1);
            if (lane == 0) wb[d] = v;
        }
        __syncwarp();
        if (lane < 24) {
            float ov = wb[lane] * inv;
            float gv = g_qkvg[qrow * (4 * CS) + 3 * CS + h * HD + lane];
            g_att[qrow * CS + h * HD + lane] = ov * gv;
        }
        __syncwarp();
    }
}

// ---------------- K5: output projection (g_att @ Wo + bo) ----------------
__global__ void outproj_kernel(const float* __restrict__ Wo, const float* __restrict__ bo,
                               float* __restrict__ out) {
    __shared__ float As[16][64];
    __shared__ float Bs[16][68];
    int bm = blockIdx.y * 64, bn = blockIdx.x * 64;
    int tid = threadIdx.x;
    int tx = tid & 15, ty = tid >> 4;
    int arow = tid >> 2, acol4 = (tid & 3) * 4;
    int brow = tid >> 4, bcol4 = (tid & 15) * 4;
    float acc[4][4] = {};

    for (int k0 = 0; k0 < CS; k0 += 16) {
        float4 av = *(const float4*)(g_att + (bm + arow) * CS + k0 + acol4);
        As[acol4 + 0][arow] = av.x;
        As[acol4 + 1][arow] = av.y;
        As[acol4 + 2][arow] = av.z;
        As[acol4 + 3][arow] = av.w;
        float4 bv = *(const float4*)(Wo + (k0 + brow) * CS + bn + bcol4);
        *(float4*)&Bs[brow][bcol4] = bv;
        __syncthreads();
        #pragma unroll
        for (int kk = 0; kk < 16; kk++) {
            float4 a4 = *(const float4*)&As[kk][ty * 4];
            float4 b4 = *(const float4*)&Bs[kk][tx * 4];
            float af[4] = {a4.x, a4.y, a4.z, a4.w};
            float bf[4] = {b4.x, b4.y, b4.z, b4.w};
            #pragma unroll
            for (int i = 0; i < 4; i++)
                #pragma unroll
                for (int j = 0; j < 4; j++)
                    acc[i][j] += af[i] * bf[j];
        }
        __syncthreads();
    }
    #pragma unroll
    for (int i = 0; i < 4; i++) {
        int row = bm + ty * 4 + i;
        float* o = out + row * CS + bn + tx * 4;
        #pragma unroll
        for (int j = 0; j < 4; j++)
            o[j] = acc[i][j] + bo[bn + tx * 4 + j];
    }
}

// ---------------- launch ----------------
extern "C" void kernel_launch(void* const* d_in, const int* in_sizes, int n_in,
                              void* d_out, int out_size) {
    (void)in_sizes; (void)n_in; (void)out_size;
    const float* a   = (const float*)d_in[0];
    const float* z   = (const float*)d_in[1];
    const float* g_a = (const float*)d_in[2];
    const float* b_a = (const float*)d_in[3];
    const float* g_z = (const float*)d_in[4];
    const float* b_z = (const float*)d_in[5];
    const float* Wz  = (const float*)d_in[6];
    const float* bz  = (const float*)d_in[7];
    const float* Wq  = (const float*)d_in[8];
    const float* Wk  = (const float*)d_in[9];
    const float* Wv  = (const float*)d_in[10];
    const float* Wg  = (const float*)d_in[11];
    const float* bg  = (const float*)d_in[12];
    const float* Wo  = (const float*)d_in[13];
    const float* bo  = (const float*)d_in[14];
    float* out = (float*)d_out;

    const int PB_SMEM = (64 * ZST + NH * CZ + 64 + 64) * 4;  // 42496 B
    cudaFuncSetAttribute(pair_bias_kernel, cudaFuncAttributeMaxDynamicSharedMemorySize, PB_SMEM);
    cudaFuncSetAttribute(attn_kernel, cudaFuncAttributeMaxDynamicSharedMemorySize, 106368);

    prep_kernel<<<1, 128>>>(g_z, b_z, Wz, bz);
    ln_a_kernel<<<NN, 128>>>(a, g_a, b_a);
    qkvg_kernel<<<dim3(6, 8, 4), 256>>>(Wq, Wk, Wv, Wg, bg);
    pair_bias_kernel<<<dim3(8, NN), 128, PB_SMEM>>>(z);
    attn_kernel<<<dim3(16, 16), 256, 106368>>>();
    outproj_kernel<<<dim3(6, 8), 256>>>(Wo, bo, out);
}